// round 1
// baseline (speedup 1.0000x reference)
#include <cuda_runtime.h>
#include <math.h>

#define N 8192
#define D 64
#define ALPHA 0.2f

// ---------------- scratch (no allocations allowed) ----------------
__device__ float g_h[N * D];        // h = x @ Wt
__device__ float g_f1[N];
__device__ float g_f2[N];
__device__ float g_f2max;
__device__ float g_f2s[N];          // f2 sorted ascending
__device__ int   g_idx[N];          // permutation
__device__ float g_P[N * D];        // e^{f2-fmax} * h   (sorted order)
__device__ float g_Q[N * D];        // e^{a(f2-fmax)} * h (sorted order)
__device__ float g_p[N];            // scalar weights
__device__ float g_q[N];
__device__ float g_Cpos[(N + 1) * D];  // suffix sums of P
__device__ float g_Cneg[(N + 1) * D];  // prefix sums of Q
__device__ float g_Dpos[N + 1];
__device__ float g_Dneg[N + 1];

// ---------------- K1: h = x@Wt, f1 = h.a1+b1, f2 = h.a2+b2 ----------------
__global__ void k_feat(const float* __restrict__ x, const float* __restrict__ Wt,
                       const float* __restrict__ a1, const float* __restrict__ b1,
                       const float* __restrict__ a2, const float* __restrict__ b2) {
    __shared__ float sW[D * D];
    __shared__ float sx[4][D];
    __shared__ float s1[8], s2[8];

    int tid = threadIdx.x;                 // 256 threads, 4 rows per block
    for (int i = tid; i < D * D; i += 256) sW[i] = Wt[i];
    int r = tid >> 6;
    int o = tid & 63;
    int row = blockIdx.x * 4 + r;
    sx[r][o] = x[row * D + o];
    __syncthreads();

    float h = 0.f;
#pragma unroll
    for (int i = 0; i < D; i++) h = fmaf(sx[r][i], sW[i * D + o], h);
    g_h[row * D + o] = h;

    float v1 = h * a1[o];
    float v2 = h * a2[o];
#pragma unroll
    for (int s = 16; s; s >>= 1) {
        v1 += __shfl_xor_sync(0xFFFFFFFFu, v1, s);
        v2 += __shfl_xor_sync(0xFFFFFFFFu, v2, s);
    }
    int w = tid >> 5;
    if ((tid & 31) == 0) { s1[w] = v1; s2[w] = v2; }
    __syncthreads();
    if (o == 0) {
        g_f1[row] = s1[2 * r] + s1[2 * r + 1] + b1[0];
        g_f2[row] = s2[2 * r] + s2[2 * r + 1] + b2[0];
    }
}

// ---------------- K2: f2max ----------------
__global__ void k_max() {
    int t = threadIdx.x;                   // 1024 threads, 1 block
    float m = -INFINITY;
    for (int i = t; i < N; i += 1024) m = fmaxf(m, g_f2[i]);
#pragma unroll
    for (int s = 16; s; s >>= 1) m = fmaxf(m, __shfl_xor_sync(0xFFFFFFFFu, m, s));
    __shared__ float sm[32];
    if ((t & 31) == 0) sm[t >> 5] = m;
    __syncthreads();
    if (t < 32) {
        float v = sm[t];
#pragma unroll
        for (int s = 16; s; s >>= 1) v = fmaxf(v, __shfl_xor_sync(0xFFFFFFFFu, v, s));
        if (t == 0) g_f2max = v;
    }
}

// ---------------- K3: single-block bitonic sort of (f2, idx) ----------------
__global__ void k_sort() {
    extern __shared__ char smem[];
    float* sk = (float*)smem;
    int*   si = (int*)(smem + N * sizeof(float));
    int t = threadIdx.x;                   // 1024 threads
    for (int i = t; i < N; i += 1024) { sk[i] = g_f2[i]; si[i] = i; }
    __syncthreads();
    for (int kk = 2; kk <= N; kk <<= 1) {
        for (int jj = kk >> 1; jj > 0; jj >>= 1) {
            for (int i = t; i < N; i += 1024) {
                int ixj = i ^ jj;
                if (ixj > i) {
                    bool up = ((i & kk) == 0);
                    float a = sk[i], b = sk[ixj];
                    if ((a > b) == up) {
                        sk[i] = b; sk[ixj] = a;
                        int ta = si[i]; si[i] = si[ixj]; si[ixj] = ta;
                    }
                }
            }
            __syncthreads();
        }
    }
    for (int i = t; i < N; i += 1024) { g_f2s[i] = sk[i]; g_idx[i] = si[i]; }
}

// ---------------- K4: gather + weight ----------------
__global__ void k_gather() {
    int tid = threadIdx.x;                 // 256 threads, 4 sorted rows per block
    int k = blockIdx.x * 4 + (tid >> 6);
    int o = tid & 63;
    float fm = g_f2max;
    float f2k = g_f2s[k];
    float p = expf(f2k - fm);
    float q = expf(ALPHA * (f2k - fm));
    float hv = g_h[g_idx[k] * D + o];
    g_P[k * D + o] = p * hv;
    g_Q[k * D + o] = q * hv;
    if (o == 0) { g_p[k] = p; g_q[k] = q; }
}

// ---------------- K5: prefix (Q->Cneg) / suffix (P->Cpos) scans ----------------
// grid = 130 blocks of 1024 threads. blocks [0,65) prefix, [65,130) suffix.
// column 64 = scalar denominators.
__global__ void k_scan() {
    int b = blockIdx.x;
    bool pos = (b >= 65);
    int c = pos ? (b - 65) : b;
    int t = threadIdx.x;                   // 1024, each owns 8 contiguous logical elems
    int base = t * 8;

    float v[8];
    if (c < D) {
        const float* src = pos ? g_P : g_Q;
#pragma unroll
        for (int s = 0; s < 8; s++) {
            int l = base + s;
            int k = pos ? (N - 1 - l) : l;
            v[s] = src[k * D + c];
        }
    } else {
        const float* src = pos ? g_p : g_q;
#pragma unroll
        for (int s = 0; s < 8; s++) {
            int l = base + s;
            int k = pos ? (N - 1 - l) : l;
            v[s] = src[k];
        }
    }
    float pref[8];
    float sum = 0.f;
#pragma unroll
    for (int s = 0; s < 8; s++) { pref[s] = sum; sum += v[s]; }

    __shared__ float sc[1024];
    sc[t] = sum;
    __syncthreads();
    for (int d2 = 1; d2 < 1024; d2 <<= 1) {
        float add = (t >= d2) ? sc[t - d2] : 0.f;
        __syncthreads();
        sc[t] += add;
        __syncthreads();
    }
    float off = (t == 0) ? 0.f : sc[t - 1];
    float total = sc[1023];

    if (c < D) {
        float* dst = pos ? g_Cpos : g_Cneg;
#pragma unroll
        for (int s = 0; s < 8; s++) {
            int l = base + s;
            float E = off + pref[s];
            if (pos) dst[(N - 1 - l) * D + c] = E + v[s];   // inclusive suffix
            else     dst[l * D + c] = E;                     // exclusive prefix
        }
        if (t == 0) dst[N * D + c] = pos ? 0.f : total;
        if (!pos && t == 0) dst[N * D + c] = total;
    } else {
        float* dst = pos ? g_Dpos : g_Dneg;
#pragma unroll
        for (int s = 0; s < 8; s++) {
            int l = base + s;
            float E = off + pref[s];
            if (pos) dst[N - 1 - l] = E + v[s];
            else     dst[l] = E;
        }
        if (t == 0) dst[N] = pos ? 0.f : total;
    }
}

// ---------------- K6: per-row combine + ELU ----------------
__global__ void k_out(float* __restrict__ out) {
    int tid = threadIdx.x;                 // 256, 4 rows per block
    int row = blockIdx.x * 4 + (tid >> 6);
    int o = tid & 63;

    float f1i = g_f1[row];
    float fm = g_f2max;
    float s0 = f1i + fm;
    float m = (s0 >= 0.f) ? s0 : ALPHA * s0;      // per-row max of lrelu logits
    float A = expf(s0 - m);                        // pos-branch row factor (<=1)
    float B = expf(ALPHA * s0 - m);                // neg-branch row factor (<=1)
    float thr = -f1i;

    // lower_bound: first k with f2s[k] >= thr
    int lo = 0, hi = N;
    while (lo < hi) {
        int mid = (lo + hi) >> 1;
        if (g_f2s[mid] < thr) lo = mid + 1; else hi = mid;
    }
    int k = lo;

    float num = A * g_Cpos[k * D + o] + B * g_Cneg[k * D + o];
    float den = A * g_Dpos[k] + B * g_Dneg[k];
    float ret = num / den;
    out[row * D + o] = (ret > 0.f) ? ret : expm1f(ret);
}

// ---------------- launch ----------------
extern "C" void kernel_launch(void* const* d_in, const int* in_sizes, int n_in,
                              void* d_out, int out_size) {
    const float* x  = (const float*)d_in[0];
    const float* Wt = (const float*)d_in[1];
    const float* a1 = (const float*)d_in[2];
    const float* b1 = (const float*)d_in[3];
    const float* a2 = (const float*)d_in[4];
    const float* b2 = (const float*)d_in[5];
    float* out = (float*)d_out;

    static bool attr_set = false;
    if (!attr_set) {
        cudaFuncSetAttribute(k_sort, cudaFuncAttributeMaxDynamicSharedMemorySize,
                             N * (sizeof(float) + sizeof(int)));
        attr_set = true;
    }

    k_feat<<<N / 4, 256>>>(x, Wt, a1, b1, a2, b2);
    k_max<<<1, 1024>>>();
    k_sort<<<1, 1024, N * (sizeof(float) + sizeof(int))>>>();
    k_gather<<<N / 4, 256>>>();
    k_scan<<<130, 1024>>>();
    k_out<<<N / 4, 256>>>(out);
}